// round 12
// baseline (speedup 1.0000x reference)
#include <cuda_runtime.h>
#include <cuda_bf16.h>
#include <cuda_fp16.h>
#include <cstdint>

#define NB  4
#define NTQ 512
#define NTK 512
#define NE  128
#define NF  256   // TWO_E
#define NT2 256   // NTK/2 (t-pairs)

// Scratch (no allocations allowed)
__device__ float    g_qproj[NB * NTQ * NE];                 // 1 MB
__device__ float    g_kproj[NB * NTK * NE];                 // 1 MB
__device__ float    g_zr[NB * NTK];                         // 1/rowsum per (b,t)
__device__ uint32_t g_ph[(size_t)NB * NT2 * NTQ];           // 2 MB  p hi, bf16 t-pairs
__device__ uint32_t g_pl[(size_t)NB * NT2 * NTQ];           // 2 MB  p lo
__device__ uint32_t g_vh[(size_t)NB * NF * NT2];            // 1 MB  value*zr hi, bf16 t-pairs
__device__ uint32_t g_vl[(size_t)NB * NF * NT2];            // 1 MB  value*zr lo

// ---- packed fp32x2 helpers ----
__device__ __forceinline__ unsigned long long pack2(float x, float y) {
    unsigned long long r;
    asm("mov.b64 %0, {%1, %2};" : "=l"(r) : "f"(x), "f"(y));
    return r;
}
__device__ __forceinline__ void ffma2(unsigned long long& d,
                                      unsigned long long a, unsigned long long b) {
    asm("fma.rn.f32x2 %0, %1, %2, %0;" : "+l"(d) : "l"(a), "l"(b));
}
__device__ __forceinline__ unsigned long long add2(unsigned long long a,
                                                   unsigned long long b) {
    unsigned long long r;
    asm("add.rn.f32x2 %0, %1, %2;" : "=l"(r) : "l"(a), "l"(b));
    return r;
}
__device__ __forceinline__ float2 unpack2(unsigned long long v) {
    float2 f;
    asm("mov.b64 {%0, %1}, %2;" : "=f"(f.x), "=f"(f.y) : "l"(v));
    return f;
}

// ---- f16x2 tanh path ----
__device__ __forceinline__ uint32_t f16x2_from_f32(float lo, float hi) {
    uint32_t r;   // first PTX source -> upper half
    asm("cvt.rn.f16x2.f32 %0, %1, %2;" : "=r"(r) : "f"(hi), "f"(lo));
    return r;
}
__device__ __forceinline__ uint32_t tanh2_f16(uint32_t x) {
    uint32_t y;
    asm("tanh.approx.f16x2 %0, %1;" : "=r"(y) : "r"(x));
    return y;
}

// ---- cp.async helpers ----
__device__ __forceinline__ uint32_t smem_u32(const void* p) {
    return (uint32_t)__cvta_generic_to_shared(p);
}
__device__ __forceinline__ void cp16(uint32_t dst, const void* src) {
    asm volatile("cp.async.ca.shared.global [%0], [%1], 16;"
                 :: "r"(dst), "l"(src) : "memory");
}
__device__ __forceinline__ void cp_commit() {
    asm volatile("cp.async.commit_group;" ::: "memory");
}
template <int N>
__device__ __forceinline__ void cp_wait() {
    asm volatile("cp.async.wait_group %0;" :: "n"(N) : "memory");
}

// ---- bf16 split helpers ----
__device__ __forceinline__ void bf16_split(float x, uint16_t& hi, uint16_t& lo) {
    __nv_bfloat16 h = __float2bfloat16(x);
    float r = x - __bfloat162float(h);
    __nv_bfloat16 l = __float2bfloat16(r);
    hi = __bfloat16_as_ushort(h);
    lo = __bfloat16_as_ushort(l);
}

// ---- mma.sync m16n8k16 bf16 (fp32 accum) ----
__device__ __forceinline__ void mma_bf16(float* c, const uint32_t* a,
                                         uint32_t b0, uint32_t b1) {
    asm volatile(
        "mma.sync.aligned.m16n8k16.row.col.f32.bf16.bf16.f32 "
        "{%0,%1,%2,%3}, {%4,%5,%6,%7}, {%8,%9}, {%0,%1,%2,%3};"
        : "+f"(c[0]), "+f"(c[1]), "+f"(c[2]), "+f"(c[3])
        : "r"(a[0]), "r"(a[1]), "r"(a[2]), "r"(a[3]), "r"(b0), "r"(b1));
}

// ---------------------------------------------------------------------------
// Kernel A: projections (unchanged from R10/R11 best).
// ---------------------------------------------------------------------------
__global__ __launch_bounds__(256) void proj_kernel(
    const float* __restrict__ query, const float* __restrict__ key,
    const float* __restrict__ W1, const float* __restrict__ W2)
{
    const float* A; const float* W; float* C;
    if (blockIdx.y == 0) { A = query; W = W1; C = g_qproj; }
    else                 { A = key;   W = W2; C = g_kproj; }

    __shared__ float As[2][32][32];
    __shared__ float Bs[2][32][128];

    const int tid = threadIdx.x;
    const int tx = tid & 31;
    const int ty = tid >> 5;
    const int row0 = blockIdx.x * 32;

    const int a_r  = tid >> 3;
    const int a_c  = (tid & 7) << 2;
    const float* a_src = A + (size_t)(row0 + a_r) * NF + a_c;

    auto issue_stage = [&](int st) {
        const int buf = st & 1;
        const int kk  = st << 5;
        cp16(smem_u32(&As[buf][a_r][a_c]), a_src + kk);
        #pragma unroll
        for (int i = 0; i < 4; i++) {
            int c  = tid + (i << 8);
            int k  = c >> 5;
            int n4 = (c & 31) << 2;
            cp16(smem_u32(&Bs[buf][k][n4]), W + (size_t)(kk + k) * NE + n4);
        }
        cp_commit();
    };

    issue_stage(0);

    unsigned long long acc2[4][2];
    #pragma unroll
    for (int i = 0; i < 4; i++) { acc2[i][0] = 0ULL; acc2[i][1] = 0ULL; }

    #pragma unroll
    for (int it = 0; it < 8; it++) {
        const int buf = it & 1;
        cp_wait<0>();
        __syncthreads();
        if (it < 7) issue_stage(it + 1);

        #pragma unroll
        for (int k4 = 0; k4 < 32; k4 += 4) {
            float a[4][4];
            #pragma unroll
            for (int i = 0; i < 4; i++) {
                float4 av = *(const float4*)&As[buf][(ty << 2) + i][k4];
                a[i][0] = av.x; a[i][1] = av.y; a[i][2] = av.z; a[i][3] = av.w;
            }
            #pragma unroll
            for (int j = 0; j < 4; j++) {
                ulonglong2 bp = *(const ulonglong2*)&Bs[buf][k4 + j][tx << 2];
                #pragma unroll
                for (int i = 0; i < 4; i++) {
                    unsigned long long aa = pack2(a[i][j], a[i][j]);
                    ffma2(acc2[i][0], aa, bp.x);
                    ffma2(acc2[i][1], aa, bp.y);
                }
            }
        }
    }

    #pragma unroll
    for (int i = 0; i < 4; i++) {
        float2 f01 = unpack2(acc2[i][0]);
        float2 f23 = unpack2(acc2[i][1]);
        float4 v = make_float4(f01.x, f01.y, f23.x, f23.y);
        *(float4*)(C + (size_t)(row0 + (ty << 2) + i) * NE + (tx << 2)) = v;
    }
}

// ---------------------------------------------------------------------------
// Kernel B: scores + exp + row-reciprocal.
// NEW: tanh via tanh.approx.f16x2 — one MUFU op per TWO elements (2x MUFU
// throughput).  Accumulation stays fp32 (f32x2 FMA).  Inputs quantized to
// f16 only at the cvt before tanh; error ~5e-4/term, vc-weighted sum -> out
// rel_err ~2-5e-4 (budget 1e-3).
// qs rows are 130 floats (65 dwords -> LDS.64 conflict-free per lane).
// Emits p as packed bf16 t-pairs (hi/lo) for the mma out kernel.
// ---------------------------------------------------------------------------
__global__ __launch_bounds__(256) void score_kernel(const float* __restrict__ vc)
{
    __shared__ float ks[8][128];
    __shared__ float qs[2][32][130];   // 65 dwords/row: LDS.64 conflict-free
    __shared__ __align__(8) float vcs[128];
    __shared__ float pex[8][32];       // per-chunk p exchange for t-pairing

    const int b   = blockIdx.y;
    const int t0  = blockIdx.x << 3;
    const int tid = threadIdx.x;
    const int w    = tid >> 5;
    const int lane = tid & 31;

    {   // k tile [8 x 128]
        int lin = tid << 2;
        int r = lin >> 7, c = lin & 127;
        *(float4*)&ks[r][c] =
            *(const float4*)(g_kproj + (size_t)(b * NTK + t0 + r) * NE + c);
    }
    if (tid < 128) vcs[tid] = vc[tid];

    const int c0    = tid & 127;
    const int rbase = tid >> 7;
    const float* qbase = g_qproj + (size_t)b * NTQ * NE + rbase * NE + c0;

    float pref[16];
    #pragma unroll
    for (int i = 0; i < 16; i++)
        pref[i] = qbase[(size_t)(2 * i) * NE];
    #pragma unroll
    for (int i = 0; i < 16; i++)
        qs[0][rbase + 2 * i][c0] = pref[i];
    __syncthreads();

    const int t = t0 + w;
    float zsum = 0.f;
    uint32_t* __restrict__ phrow = g_ph + ((size_t)b * NT2 + (t0 >> 1) + w) * NTQ;
    uint32_t* __restrict__ plrow = g_pl + ((size_t)b * NT2 + (t0 >> 1) + w) * NTQ;

    for (int ch = 0; ch < 16; ch++) {
        const int buf = ch & 1;
        if (ch < 15) {
            const float* src = qbase + (size_t)(ch + 1) * 32 * NE;
            #pragma unroll
            for (int i = 0; i < 16; i++)
                pref[i] = src[(size_t)(2 * i) * NE];
        }

        const float* __restrict__ kr = ks[w];          // warp broadcast
        const float* __restrict__ q0 = qs[buf][lane];
        unsigned long long acc2 = 0ULL;
        #pragma unroll 16
        for (int j = 0; j < 64; j++) {                 // 2 elements per iter
            unsigned long long k2 = *(const unsigned long long*)(kr + 2 * j);
            unsigned long long q2 = *(const unsigned long long*)(q0 + 2 * j);
            float2 s = unpack2(add2(k2, q2));
            uint32_t h = tanh2_f16(f16x2_from_f32(s.x, s.y));
            __half2 hh = *reinterpret_cast<__half2*>(&h);
            float2 tv = __half22float2(hh);
            unsigned long long vc2 = *(const unsigned long long*)(vcs + 2 * j);
            ffma2(acc2, pack2(tv.x, tv.y), vc2);
        }
        float2 ar = unpack2(acc2);
        float p0 = __expf(ar.x + ar.y);
        pex[w][lane] = p0;
        zsum += p0;

        __syncthreads();               // pex visible; qs[buf] reads done
        if (w < 4) {                   // warps 0-3 emit packed t-pairs
            float pe = pex[2 * w][lane];
            float po = pex[2 * w + 1][lane];
            uint16_t he, le, ho, lo;
            bf16_split(pe, he, le);
            bf16_split(po, ho, lo);
            phrow[ch * 32 + lane] = ((uint32_t)ho << 16) | he;
            plrow[ch * 32 + lane] = ((uint32_t)lo << 16) | le;
        }
        if (ch < 15) {
            #pragma unroll
            for (int i = 0; i < 16; i++)
                qs[buf ^ 1][rbase + 2 * i][c0] = pref[i];
        }
        __syncthreads();               // qs refilled; pex consumed before rewrite
    }

    #pragma unroll
    for (int off = 16; off; off >>= 1)
        zsum += __shfl_xor_sync(0xffffffffu, zsum, off);
    if (lane == 0) g_zr[b * NTK + t] = 1.0f / zsum;
}

// ---------------------------------------------------------------------------
// Kernel B2: value*zr -> packed bf16 t-pairs (hi/lo). 262144 pairs.
// ---------------------------------------------------------------------------
__global__ __launch_bounds__(256) void conv_kernel(const float* __restrict__ value)
{
    int idx = blockIdx.x * 256 + threadIdx.x;      // [b][d][t2]
    int b  = idx >> 16;
    int d  = (idx >> 8) & 255;
    int t2 = idx & 255;

    float2 v2 = *(const float2*)(value + ((size_t)(b * NF + d) << 9) + 2 * t2);
    float e = v2.x * g_zr[b * NTK + 2 * t2];
    float o = v2.y * g_zr[b * NTK + 2 * t2 + 1];

    uint16_t he, le, ho, lo;
    bf16_split(e, he, le);
    bf16_split(o, ho, lo);
    g_vh[idx] = ((uint32_t)ho << 16) | he;
    g_vl[idx] = ((uint32_t)lo << 16) | le;
}

// ---------------------------------------------------------------------------
// Kernel C: out via mma.sync bf16 3-term split (unchanged from R11 winner).
// ---------------------------------------------------------------------------
__global__ __launch_bounds__(256) void out_kernel(float* __restrict__ out)
{
    __shared__ uint32_t Ah[2][64][20];
    __shared__ uint32_t Al[2][64][20];
    __shared__ uint32_t Bh[2][16][72];
    __shared__ uint32_t Bl[2][16][72];

    const int b  = blockIdx.z;
    const int n0 = blockIdx.x << 6;
    const int m0 = blockIdx.y << 6;
    const int tid = threadIdx.x;
    const int w    = tid >> 5;
    const int lane = tid & 31;
    const int wm   = w >> 2;
    const int wn   = w & 3;
    const int grp  = lane >> 2;
    const int tig  = lane & 3;

    const uint32_t* vhp = g_vh + (size_t)(b * NF + m0) * NT2;
    const uint32_t* vlp = g_vl + (size_t)(b * NF + m0) * NT2;
    const uint32_t* php = g_ph + (size_t)b * NT2 * NTQ + n0;
    const uint32_t* plp = g_pl + (size_t)b * NT2 * NTQ + n0;

    const int am = tid >> 2, ac = (tid & 3) << 2;
    const int br = tid >> 4, bc = (tid & 15) << 2;

    auto issue_stage = [&](int st) {
        const int bufi = st & 1;
        const int kk2  = st << 4;
        cp16(smem_u32(&Ah[bufi][am][ac]), vhp + (size_t)am * NT2 + kk2 + ac);
        cp16(smem_u32(&Al[bufi][am][ac]), vlp + (size_t)am * NT2 + kk2 + ac);
        cp16(smem_u32(&Bh[bufi][br][bc]), php + (size_t)(kk2 + br) * NTQ + bc);
        cp16(smem_u32(&Bl[bufi][br][bc]), plp + (size_t)(kk2 + br) * NTQ + bc);
        cp_commit();
    };

    issue_stage(0);

    float acc[2][2][4];
    #pragma unroll
    for (int i = 0; i < 2; i++)
        #pragma unroll
        for (int j = 0; j < 2; j++)
            #pragma unroll
            for (int r = 0; r < 4; r++) acc[i][j][r] = 0.f;

    #pragma unroll
    for (int it = 0; it < 16; it++) {
        const int bufi = it & 1;
        cp_wait<0>();
        __syncthreads();
        if (it < 15) issue_stage(it + 1);

        #pragma unroll
        for (int s = 0; s < 2; s++) {
            uint32_t ah[2][4], al[2][4];
            #pragma unroll
            for (int mf = 0; mf < 2; mf++) {
                const int mb = wm * 32 + mf * 16;
                const int kc = s * 8 + tig;
                ah[mf][0] = Ah[bufi][mb + grp    ][kc];
                ah[mf][1] = Ah[bufi][mb + grp + 8][kc];
                ah[mf][2] = Ah[bufi][mb + grp    ][kc + 4];
                ah[mf][3] = Ah[bufi][mb + grp + 8][kc + 4];
                al[mf][0] = Al[bufi][mb + grp    ][kc];
                al[mf][1] = Al[bufi][mb + grp + 8][kc];
                al[mf][2] = Al[bufi][mb + grp    ][kc + 4];
                al[mf][3] = Al[bufi][mb + grp + 8][kc + 4];
            }
            #pragma unroll
            for (int nf = 0; nf < 2; nf++) {
                const int nb = wn * 16 + nf * 8 + grp;
                const int kr = s * 8 + tig;
                uint32_t bh0 = Bh[bufi][kr    ][nb];
                uint32_t bh1 = Bh[bufi][kr + 4][nb];
                uint32_t bl0 = Bl[bufi][kr    ][nb];
                uint32_t bl1 = Bl[bufi][kr + 4][nb];
                #pragma unroll
                for (int mf = 0; mf < 2; mf++) {
                    mma_bf16(acc[mf][nf], ah[mf], bh0, bh1);
                    mma_bf16(acc[mf][nf], ah[mf], bl0, bl1);
                    mma_bf16(acc[mf][nf], al[mf], bh0, bh1);
                }
            }
        }
    }

    #pragma unroll
    for (int mf = 0; mf < 2; mf++) {
        #pragma unroll
        for (int nf = 0; nf < 2; nf++) {
            const int row = m0 + wm * 32 + mf * 16 + grp;
            const int col = n0 + wn * 16 + nf * 8 + tig * 2;
            float* dst0 = out + (size_t)(b * NF + row) * NTQ + col;
            float* dst1 = dst0 + 8 * NTQ;
            *(float2*)dst0 = make_float2(acc[mf][nf][0], acc[mf][nf][1]);
            *(float2*)dst1 = make_float2(acc[mf][nf][2], acc[mf][nf][3]);
        }
    }
}

// ---------------------------------------------------------------------------
extern "C" void kernel_launch(void* const* d_in, const int* in_sizes, int n_in,
                              void* d_out, int out_size)
{
    const float* query = (const float*)d_in[0];
    const float* key   = (const float*)d_in[1];
    const float* value = (const float*)d_in[2];
    const float* W1    = (const float*)d_in[3];
    const float* W2    = (const float*)d_in[4];
    const float* vc    = (const float*)d_in[5];
    float* out = (float*)d_out;

    proj_kernel <<<dim3(64, 2), 256>>>(query, key, W1, W2);
    score_kernel<<<dim3(64, 4), 256>>>(vc);
    conv_kernel <<<1024, 256>>>(value);
    out_kernel  <<<dim3(8, 4, 4), 256>>>(out);
}

// round 13
// speedup vs baseline: 1.0040x; 1.0040x over previous
#include <cuda_runtime.h>
#include <cuda_bf16.h>
#include <cstdint>

#define NB  4
#define NTQ 512
#define NTK 512
#define NE  128
#define NF  256   // TWO_E
#define NT2 256   // NTK/2 (t-pairs)

// Scratch (no allocations allowed)
__device__ float    g_qproj[NB * NTQ * NE];                 // 1 MB
__device__ float    g_kproj[NB * NTK * NE];                 // 1 MB
__device__ float    g_zr[NB * NTK];                         // 1/rowsum per (b,t)
__device__ uint32_t g_ph[(size_t)NB * NT2 * NTQ];           // 2 MB  p hi, bf16 t-pairs
__device__ uint32_t g_pl[(size_t)NB * NT2 * NTQ];           // 2 MB  p lo
__device__ uint32_t g_vh[(size_t)NB * NF * NT2];            // 1 MB  value*zr hi, bf16 t-pairs
__device__ uint32_t g_vl[(size_t)NB * NF * NT2];            // 1 MB  value*zr lo

__device__ __forceinline__ float tanh_fast(float x) {
    float y;
    asm("tanh.approx.f32 %0, %1;" : "=f"(y) : "f"(x));
    return y;
}

// ---- packed fp32x2 helpers ----
__device__ __forceinline__ unsigned long long pack2(float x, float y) {
    unsigned long long r;
    asm("mov.b64 %0, {%1, %2};" : "=l"(r) : "f"(x), "f"(y));
    return r;
}
__device__ __forceinline__ void ffma2(unsigned long long& d,
                                      unsigned long long a, unsigned long long b) {
    asm("fma.rn.f32x2 %0, %1, %2, %0;" : "+l"(d) : "l"(a), "l"(b));
}
__device__ __forceinline__ float2 unpack2(unsigned long long v) {
    float2 f;
    asm("mov.b64 {%0, %1}, %2;" : "=f"(f.x), "=f"(f.y) : "l"(v));
    return f;
}

// ---- cp.async helpers ----
__device__ __forceinline__ uint32_t smem_u32(const void* p) {
    return (uint32_t)__cvta_generic_to_shared(p);
}
__device__ __forceinline__ void cp16(uint32_t dst, const void* src) {
    asm volatile("cp.async.ca.shared.global [%0], [%1], 16;"
                 :: "r"(dst), "l"(src) : "memory");
}
__device__ __forceinline__ void cp_commit() {
    asm volatile("cp.async.commit_group;" ::: "memory");
}
template <int N>
__device__ __forceinline__ void cp_wait() {
    asm volatile("cp.async.wait_group %0;" :: "n"(N) : "memory");
}

// ---- bf16 split helpers ----
__device__ __forceinline__ void bf16_split(float x, uint16_t& hi, uint16_t& lo) {
    __nv_bfloat16 h = __float2bfloat16(x);
    float r = x - __bfloat162float(h);
    __nv_bfloat16 l = __float2bfloat16(r);
    hi = __bfloat16_as_ushort(h);
    lo = __bfloat16_as_ushort(l);
}

// ---- mma.sync m16n8k16 bf16 (fp32 accum) ----
__device__ __forceinline__ void mma_bf16(float* c, const uint32_t* a,
                                         uint32_t b0, uint32_t b1) {
    asm volatile(
        "mma.sync.aligned.m16n8k16.row.col.f32.bf16.bf16.f32 "
        "{%0,%1,%2,%3}, {%4,%5,%6,%7}, {%8,%9}, {%0,%1,%2,%3};"
        : "+f"(c[0]), "+f"(c[1]), "+f"(c[2]), "+f"(c[3])
        : "r"(a[0]), "r"(a[1]), "r"(a[2]), "r"(a[3]), "r"(b0), "r"(b1));
}

// ---------------------------------------------------------------------------
// Kernel A: projections (unchanged from R10/R11 best).
// ---------------------------------------------------------------------------
__global__ __launch_bounds__(256) void proj_kernel(
    const float* __restrict__ query, const float* __restrict__ key,
    const float* __restrict__ W1, const float* __restrict__ W2)
{
    const float* A; const float* W; float* C;
    if (blockIdx.y == 0) { A = query; W = W1; C = g_qproj; }
    else                 { A = key;   W = W2; C = g_kproj; }

    __shared__ float As[2][32][32];
    __shared__ float Bs[2][32][128];

    const int tid = threadIdx.x;
    const int tx = tid & 31;
    const int ty = tid >> 5;
    const int row0 = blockIdx.x * 32;

    const int a_r  = tid >> 3;
    const int a_c  = (tid & 7) << 2;
    const float* a_src = A + (size_t)(row0 + a_r) * NF + a_c;

    auto issue_stage = [&](int st) {
        const int buf = st & 1;
        const int kk  = st << 5;
        cp16(smem_u32(&As[buf][a_r][a_c]), a_src + kk);
        #pragma unroll
        for (int i = 0; i < 4; i++) {
            int c  = tid + (i << 8);
            int k  = c >> 5;
            int n4 = (c & 31) << 2;
            cp16(smem_u32(&Bs[buf][k][n4]), W + (size_t)(kk + k) * NE + n4);
        }
        cp_commit();
    };

    issue_stage(0);

    unsigned long long acc2[4][2];
    #pragma unroll
    for (int i = 0; i < 4; i++) { acc2[i][0] = 0ULL; acc2[i][1] = 0ULL; }

    #pragma unroll
    for (int it = 0; it < 8; it++) {
        const int buf = it & 1;
        cp_wait<0>();
        __syncthreads();
        if (it < 7) issue_stage(it + 1);

        #pragma unroll
        for (int k4 = 0; k4 < 32; k4 += 4) {
            float a[4][4];
            #pragma unroll
            for (int i = 0; i < 4; i++) {
                float4 av = *(const float4*)&As[buf][(ty << 2) + i][k4];
                a[i][0] = av.x; a[i][1] = av.y; a[i][2] = av.z; a[i][3] = av.w;
            }
            #pragma unroll
            for (int j = 0; j < 4; j++) {
                ulonglong2 bp = *(const ulonglong2*)&Bs[buf][k4 + j][tx << 2];
                #pragma unroll
                for (int i = 0; i < 4; i++) {
                    unsigned long long aa = pack2(a[i][j], a[i][j]);
                    ffma2(acc2[i][0], aa, bp.x);
                    ffma2(acc2[i][1], aa, bp.y);
                }
            }
        }
    }

    #pragma unroll
    for (int i = 0; i < 4; i++) {
        float2 f01 = unpack2(acc2[i][0]);
        float2 f23 = unpack2(acc2[i][1]);
        float4 v = make_float4(f01.x, f01.y, f23.x, f23.y);
        *(float4*)(C + (size_t)(row0 + (ty << 2) + i) * NE + (tx << 2)) = v;
    }
}

// ---------------------------------------------------------------------------
// Kernel B: scores + exp + row-reciprocal (R11 f32-tanh form — reverted:
// f16x2 tanh proved 2 MUFU passes = neutral speed, worse accuracy).
// Emits p as packed bf16 t-pairs (hi/lo) for the mma out kernel.
// ---------------------------------------------------------------------------
__global__ __launch_bounds__(256) void score_kernel(const float* __restrict__ vc)
{
    __shared__ float ks[8][128];
    __shared__ float qs[2][32][129];
    __shared__ float vcs[128];
    __shared__ float pex[8][32];       // per-chunk p exchange for t-pairing

    const int b   = blockIdx.y;
    const int t0  = blockIdx.x << 3;
    const int tid = threadIdx.x;
    const int w    = tid >> 5;
    const int lane = tid & 31;

    {   // k tile [8 x 128]
        int lin = tid << 2;
        int r = lin >> 7, c = lin & 127;
        *(float4*)&ks[r][c] =
            *(const float4*)(g_kproj + (size_t)(b * NTK + t0 + r) * NE + c);
    }
    if (tid < 128) vcs[tid] = vc[tid];

    const int c0    = tid & 127;
    const int rbase = tid >> 7;
    const float* qbase = g_qproj + (size_t)b * NTQ * NE + rbase * NE + c0;

    float pref[16];
    #pragma unroll
    for (int i = 0; i < 16; i++)
        pref[i] = qbase[(size_t)(2 * i) * NE];
    #pragma unroll
    for (int i = 0; i < 16; i++)
        qs[0][rbase + 2 * i][c0] = pref[i];
    __syncthreads();

    const int t = t0 + w;
    float zsum = 0.f;
    uint32_t* __restrict__ phrow = g_ph + ((size_t)b * NT2 + (t0 >> 1) + w) * NTQ;
    uint32_t* __restrict__ plrow = g_pl + ((size_t)b * NT2 + (t0 >> 1) + w) * NTQ;

    for (int ch = 0; ch < 16; ch++) {
        const int buf = ch & 1;
        if (ch < 15) {
            const float* src = qbase + (size_t)(ch + 1) * 32 * NE;
            #pragma unroll
            for (int i = 0; i < 16; i++)
                pref[i] = src[(size_t)(2 * i) * NE];
        }

        const float* __restrict__ kr = ks[w];
        const float* __restrict__ q0 = qs[buf][lane];
        float acc0 = 0.f;
        #pragma unroll 16
        for (int e = 0; e < 128; e++)
            acc0 += vcs[e] * tanh_fast(kr[e] + q0[e]);

        float p0 = __expf(acc0);
        pex[w][lane] = p0;
        zsum += p0;

        __syncthreads();               // pex visible; qs[buf] reads done
        if (w < 4) {                   // warps 0-3 emit packed t-pairs
            float pe = pex[2 * w][lane];
            float po = pex[2 * w + 1][lane];
            uint16_t he, le, ho, lo;
            bf16_split(pe, he, le);
            bf16_split(po, ho, lo);
            phrow[ch * 32 + lane] = ((uint32_t)ho << 16) | he;
            plrow[ch * 32 + lane] = ((uint32_t)lo << 16) | le;
        }
        if (ch < 15) {
            #pragma unroll
            for (int i = 0; i < 16; i++)
                qs[buf ^ 1][rbase + 2 * i][c0] = pref[i];
        }
        __syncthreads();               // qs refilled; pex consumed before rewrite
    }

    #pragma unroll
    for (int off = 16; off; off >>= 1)
        zsum += __shfl_xor_sync(0xffffffffu, zsum, off);
    if (lane == 0) g_zr[b * NTK + t] = 1.0f / zsum;
}

// ---------------------------------------------------------------------------
// Kernel B2: value*zr -> packed bf16 t-pairs (hi/lo). 262144 pairs.
// ---------------------------------------------------------------------------
__global__ __launch_bounds__(256) void conv_kernel(const float* __restrict__ value)
{
    int idx = blockIdx.x * 256 + threadIdx.x;      // [b][d][t2]
    int b  = idx >> 16;
    int d  = (idx >> 8) & 255;
    int t2 = idx & 255;

    float2 v2 = *(const float2*)(value + ((size_t)(b * NF + d) << 9) + 2 * t2);
    float e = v2.x * g_zr[b * NTK + 2 * t2];
    float o = v2.y * g_zr[b * NTK + 2 * t2 + 1];

    uint16_t he, le, ho, lo;
    bf16_split(e, he, le);
    bf16_split(o, ho, lo);
    g_vh[idx] = ((uint32_t)ho << 16) | he;
    g_vl[idx] = ((uint32_t)lo << 16) | le;
}

// ---------------------------------------------------------------------------
// Kernel C: out via mma.sync bf16 3-term split.
// NEW: 512 threads, 16 warps in a 4m x 4n grid, warp tile 16x16 (1 m-frag x
// 2 n-frags).  Same 64x64 block tile, same 128-block single wave, same smem.
// Halves each warp's LDS->mma chain and doubles warps/SMSP (2 -> 4) to hide
// fragment-gather latency (R12: issue=12%, tensor=17%).
// ---------------------------------------------------------------------------
__global__ __launch_bounds__(512) void out_kernel(float* __restrict__ out)
{
    __shared__ uint32_t Ah[2][64][20];   // data cols 0..15 (16 t2)
    __shared__ uint32_t Al[2][64][20];
    __shared__ uint32_t Bh[2][16][72];   // data cols 0..63 (64 q)
    __shared__ uint32_t Bl[2][16][72];

    const int b  = blockIdx.z;
    const int n0 = blockIdx.x << 6;
    const int m0 = blockIdx.y << 6;
    const int tid = threadIdx.x;
    const int w    = tid >> 5;
    const int lane = tid & 31;
    const int wm   = w >> 2;             // 0-3
    const int wn   = w & 3;              // 0-3
    const int grp  = lane >> 2;          // 0-7
    const int tig  = lane & 3;           // 0-3

    const uint32_t* vhp = g_vh + (size_t)(b * NF + m0) * NT2;
    const uint32_t* vlp = g_vl + (size_t)(b * NF + m0) * NT2;
    const uint32_t* php = g_ph + (size_t)b * NT2 * NTQ + n0;
    const uint32_t* plp = g_pl + (size_t)b * NT2 * NTQ + n0;

    // cp.async mapping: 512 threads, 1 A-chunk + 1 B-chunk each.
    const int asel = tid >> 8;                   // 0 -> Ah, 1 -> Al
    const int am = (tid & 255) >> 2, ac = (tid & 3) << 2;
    const int br = (tid & 255) >> 4, bc = (tid & 15) << 2;

    auto issue_stage = [&](int st) {
        const int bufi = st & 1;
        const int kk2  = st << 4;
        if (asel == 0) {
            cp16(smem_u32(&Ah[bufi][am][ac]), vhp + (size_t)am * NT2 + kk2 + ac);
            cp16(smem_u32(&Bh[bufi][br][bc]), php + (size_t)(kk2 + br) * NTQ + bc);
        } else {
            cp16(smem_u32(&Al[bufi][am][ac]), vlp + (size_t)am * NT2 + kk2 + ac);
            cp16(smem_u32(&Bl[bufi][br][bc]), plp + (size_t)(kk2 + br) * NTQ + bc);
        }
        cp_commit();
    };

    issue_stage(0);

    float acc[2][4];                     // [nf][reg]
    #pragma unroll
    for (int j = 0; j < 2; j++)
        #pragma unroll
        for (int r = 0; r < 4; r++) acc[j][r] = 0.f;

    #pragma unroll
    for (int it = 0; it < 16; it++) {
        const int bufi = it & 1;
        cp_wait<0>();
        __syncthreads();
        if (it < 15) issue_stage(it + 1);

        #pragma unroll
        for (int s = 0; s < 2; s++) {            // two k16 steps per stage
            uint32_t ah[4], al[4];
            {
                const int mb = wm * 16;
                const int kc = s * 8 + tig;
                ah[0] = Ah[bufi][mb + grp    ][kc];
                ah[1] = Ah[bufi][mb + grp + 8][kc];
                ah[2] = Ah[bufi][mb + grp    ][kc + 4];
                ah[3] = Ah[bufi][mb + grp + 8][kc + 4];
                al[0] = Al[bufi][mb + grp    ][kc];
                al[1] = Al[bufi][mb + grp + 8][kc];
                al[2] = Al[bufi][mb + grp    ][kc + 4];
                al[3] = Al[bufi][mb + grp + 8][kc + 4];
            }
            #pragma unroll
            for (int nf = 0; nf < 2; nf++) {
                const int nb = wn * 16 + nf * 8 + grp;
                const int kr = s * 8 + tig;
                uint32_t bh0 = Bh[bufi][kr    ][nb];
                uint32_t bh1 = Bh[bufi][kr + 4][nb];
                uint32_t bl0 = Bl[bufi][kr    ][nb];
                uint32_t bl1 = Bl[bufi][kr + 4][nb];
                mma_bf16(acc[nf], ah, bh0, bh1);
                mma_bf16(acc[nf], ah, bl0, bl1);
                mma_bf16(acc[nf], al, bh0, bh1);
            }
        }
    }

    // epilogue
    #pragma unroll
    for (int nf = 0; nf < 2; nf++) {
        const int row = m0 + wm * 16 + grp;
        const int col = n0 + wn * 16 + nf * 8 + tig * 2;
        float* dst0 = out + (size_t)(b * NF + row) * NTQ + col;
        float* dst1 = dst0 + 8 * NTQ;
        *(float2*)dst0 = make_float2(acc[nf][0], acc[nf][1]);
        *(float2*)dst1 = make_float2(acc[nf][2], acc[nf][3]);
    }
}

// ---------------------------------------------------------------------------
extern "C" void kernel_launch(void* const* d_in, const int* in_sizes, int n_in,
                              void* d_out, int out_size)
{
    const float* query = (const float*)d_in[0];
    const float* key   = (const float*)d_in[1];
    const float* value = (const float*)d_in[2];
    const float* W1    = (const float*)d_in[3];
    const float* W2    = (const float*)d_in[4];
    const float* vc    = (const float*)d_in[5];
    float* out = (float*)d_out;

    proj_kernel <<<dim3(64, 2), 256>>>(query, key, W1, W2);
    score_kernel<<<dim3(64, 4), 256>>>(vc);
    conv_kernel <<<1024, 256>>>(value);
    out_kernel  <<<dim3(8, 4, 4), 512>>>(out);
}